// round 5
// baseline (speedup 1.0000x reference)
#include <cuda_runtime.h>
#include <math.h>
#include <stdint.h>

// Problem dims
constexpr int Bb = 128, Ss = 64, Ee = 256, Hh = 256, Dd = 256, Aa = 256, Vv = 10000;
constexpr int CAT = Dd + 2*Hh + Ee;   // 1024
constexpr int RNK = Ee + 2*Hh;        // 768

// ---------------- scratch ---------------------------------------------------
constexpr size_t OFF_EMB   = 0;
constexpr size_t OFF_XPF   = OFF_EMB   + (size_t)Bb*Ss*Ee;
constexpr size_t OFF_XPB   = OFF_XPF   + (size_t)Bb*Ss*3*Hh;
constexpr size_t OFF_ENCO  = OFF_XPB   + (size_t)Bb*Ss*3*Hh;
constexpr size_t OFF_ENCP  = OFF_ENCO  + (size_t)Bb*Ss*2*Hh;
constexpr size_t OFF_HF0   = OFF_ENCP  + (size_t)Bb*Ss*Aa;
constexpr size_t OFF_HF1   = OFF_HF0   + (size_t)Bb*Hh;
constexpr size_t OFF_HB0   = OFF_HF1   + (size_t)Bb*Hh;
constexpr size_t OFF_HB1   = OFF_HB0   + (size_t)Bb*Hh;
constexpr size_t OFF_HID0  = OFF_HB1   + (size_t)Bb*Hh;
constexpr size_t OFF_HID1  = OFF_HID0  + (size_t)Bb*Dd;
constexpr size_t OFF_FCIN  = OFF_HID1  + (size_t)Bb*Dd;
constexpr size_t OFF_RNIN  = OFF_FCIN  + (size_t)Bb*2*Hh;
constexpr size_t OFF_CAT   = OFF_RNIN  + (size_t)Bb*RNK;
constexpr size_t OFF_ATTWT = OFF_CAT   + (size_t)Bb*CAT;
constexpr size_t OFF_SLOT  = OFF_ATTWT + (size_t)Dd*Aa;
constexpr size_t SCR_TOTAL = OFF_SLOT  + (size_t)2*Bb;

__device__ __align__(256) float g_scratch[SCR_TOTAL];

__device__ __forceinline__ float sigf(float x) { return 1.f / (1.f + expf(-x)); }

__device__ __forceinline__ unsigned int fmono(float x) {
    unsigned int b = __float_as_uint(x);
    return (b & 0x80000000u) ? ~b : (b | 0x80000000u);
}

// =====================================================================
//  gemm88: C[M,N] = A[M,K] @ B[N,K]^T (+bias), fused argmax option.
//  BM=64, BN=64, BK=16, TM=8, TN=8, 64 threads, double-buffered.
//  LDS:FMA = 16:64 floats = 0.25/FMA -> exactly at smem/fma balance.
//  Requires M%64==0, K%16==0, lda%4==0, ldb%4==0, 16B-aligned bases.
// =====================================================================
template<int AMAX>
__global__ __launch_bounds__(64)
void gemm88(const float* __restrict__ A, int lda,
            const float* __restrict__ Bm, int ldb,
            float* __restrict__ C, int ldc,
            const float* __restrict__ bias,
            int M, int N, int K,
            unsigned long long* __restrict__ slots)
{
    __shared__ __align__(16) float sA[2][16][68];
    __shared__ __align__(16) float sB[2][16][68];
    const int tid = threadIdx.x;
    const int tx = tid & 7, ty = tid >> 3;            // 8 x 8 threads
    const int row0 = blockIdx.y * 64, col0 = blockIdx.x * 64;

    const float* Aptr = A + (size_t)(row0 + tid) * lda;
    const int gnl = col0 + tid;
    const int gnc = (gnl < N) ? gnl : (N - 1);
    const float* Bptr = Bm + (size_t)gnc * ldb;
    const bool bval = (gnl < N);

    float4 pa[4], pb[4];
    #pragma unroll
    for (int c = 0; c < 4; c++) {
        pa[c] = *reinterpret_cast<const float4*>(Aptr + 4*c);
        pb[c] = bval ? *reinterpret_cast<const float4*>(Bptr + 4*c)
                     : make_float4(0.f, 0.f, 0.f, 0.f);
    }
    #pragma unroll
    for (int c = 0; c < 4; c++) {
        sA[0][4*c+0][tid] = pa[c].x; sA[0][4*c+1][tid] = pa[c].y;
        sA[0][4*c+2][tid] = pa[c].z; sA[0][4*c+3][tid] = pa[c].w;
        sB[0][4*c+0][tid] = pb[c].x; sB[0][4*c+1][tid] = pb[c].y;
        sB[0][4*c+2][tid] = pb[c].z; sB[0][4*c+3][tid] = pb[c].w;
    }
    __syncthreads();

    float acc[8][8];
    #pragma unroll
    for (int i = 0; i < 8; i++)
        #pragma unroll
        for (int j = 0; j < 8; j++) acc[i][j] = 0.f;

    int buf = 0;
    for (int k0 = 16; k0 <= K; k0 += 16) {
        const bool has_next = (k0 < K);
        if (has_next) {
            #pragma unroll
            for (int c = 0; c < 4; c++) {
                pa[c] = *reinterpret_cast<const float4*>(Aptr + k0 + 4*c);
                pb[c] = bval ? *reinterpret_cast<const float4*>(Bptr + k0 + 4*c)
                             : make_float4(0.f, 0.f, 0.f, 0.f);
            }
        }
        #pragma unroll
        for (int kk = 0; kk < 16; kk++) {
            float4 av0 = *reinterpret_cast<const float4*>(&sA[buf][kk][ty*8]);
            float4 av1 = *reinterpret_cast<const float4*>(&sA[buf][kk][ty*8+4]);
            float4 bv0 = *reinterpret_cast<const float4*>(&sB[buf][kk][tx*8]);
            float4 bv1 = *reinterpret_cast<const float4*>(&sB[buf][kk][tx*8+4]);
            float a[8] = {av0.x, av0.y, av0.z, av0.w, av1.x, av1.y, av1.z, av1.w};
            float b[8] = {bv0.x, bv0.y, bv0.z, bv0.w, bv1.x, bv1.y, bv1.z, bv1.w};
            #pragma unroll
            for (int i = 0; i < 8; i++)
                #pragma unroll
                for (int j = 0; j < 8; j++) acc[i][j] += a[i] * b[j];
        }
        if (has_next) {
            const int nb = buf ^ 1;
            #pragma unroll
            for (int c = 0; c < 4; c++) {
                sA[nb][4*c+0][tid] = pa[c].x; sA[nb][4*c+1][tid] = pa[c].y;
                sA[nb][4*c+2][tid] = pa[c].z; sA[nb][4*c+3][tid] = pa[c].w;
                sB[nb][4*c+0][tid] = pb[c].x; sB[nb][4*c+1][tid] = pb[c].y;
                sB[nb][4*c+2][tid] = pb[c].z; sB[nb][4*c+3][tid] = pb[c].w;
            }
            __syncthreads();
            buf = nb;
        }
    }

    float bb[8];
    #pragma unroll
    for (int j = 0; j < 8; j++) {
        int gn = col0 + tx*8 + j;
        bb[j] = (bias && gn < N) ? bias[gn] : 0.f;
    }

    #pragma unroll
    for (int i = 0; i < 8; i++) {
        const int gm = row0 + ty*8 + i;
        float bestv = -INFINITY; int besti = 0;
        #pragma unroll
        for (int j = 0; j < 8; j++) {
            int gn = col0 + tx*8 + j;
            if (gn < N) {
                float v = acc[i][j] + bb[j];
                C[(size_t)gm * ldc + gn] = v;
                if (AMAX) { if (v > bestv) { bestv = v; besti = gn; } }
            }
        }
        if (AMAX) {
            unsigned long long key =
                ((unsigned long long)fmono(bestv) << 32) |
                (unsigned long long)(0xFFFFFFFFu - (unsigned)besti);
            #pragma unroll
            for (int o = 4; o; o >>= 1) {
                unsigned long long ok = __shfl_xor_sync(0xffffffffu, key, o);
                if (ok > key) key = ok;
            }
            if (tx == 0) atomicMax(&slots[gm], key);
        }
    }
}

// =====================================================================
//  gemmL: big one-time GEMMs (unchanged, passing).
// =====================================================================
__global__ __launch_bounds__(256)
void gemmL(const float* __restrict__ A, int lda,
           const float* __restrict__ Bm, int ldb,
           float* __restrict__ C, int ldc,
           const float* __restrict__ bias,
           int M, int N, int K)
{
    __shared__ __align__(16) float sA[2][16][132];
    __shared__ __align__(16) float sB[2][16][68];
    const int tid = threadIdx.x;
    const int tx = tid & 15, ty = tid >> 4;
    const int row0 = blockIdx.y * 128, col0 = blockIdx.x * 64;
    const int lr = tid >> 2;
    const int lc = (tid & 3) * 4;

    const float* Aptr0 = A + (size_t)(row0 + lr) * lda + lc;
    const float* Aptr1 = A + (size_t)(row0 + 64 + lr) * lda + lc;
    const int gnl = col0 + lr;
    const int gnc = (gnl < N) ? gnl : (N - 1);
    const float* Bptr = Bm + (size_t)gnc * ldb + lc;
    const bool bval = (gnl < N);

    float4 pa0 = *reinterpret_cast<const float4*>(Aptr0);
    float4 pa1 = *reinterpret_cast<const float4*>(Aptr1);
    float4 pb  = *reinterpret_cast<const float4*>(Bptr);
    if (!bval) pb = make_float4(0.f, 0.f, 0.f, 0.f);

    sA[0][lc+0][lr]    = pa0.x; sA[0][lc+1][lr]    = pa0.y;
    sA[0][lc+2][lr]    = pa0.z; sA[0][lc+3][lr]    = pa0.w;
    sA[0][lc+0][64+lr] = pa1.x; sA[0][lc+1][64+lr] = pa1.y;
    sA[0][lc+2][64+lr] = pa1.z; sA[0][lc+3][64+lr] = pa1.w;
    sB[0][lc+0][lr] = pb.x; sB[0][lc+1][lr] = pb.y;
    sB[0][lc+2][lr] = pb.z; sB[0][lc+3][lr] = pb.w;
    __syncthreads();

    float acc[8][4];
    #pragma unroll
    for (int i = 0; i < 8; i++)
        #pragma unroll
        for (int j = 0; j < 4; j++) acc[i][j] = 0.f;

    int buf = 0;
    for (int k0 = 16; k0 <= K; k0 += 16) {
        const bool has_next = (k0 < K);
        if (has_next) {
            pa0 = *reinterpret_cast<const float4*>(Aptr0 + k0);
            pa1 = *reinterpret_cast<const float4*>(Aptr1 + k0);
            pb  = *reinterpret_cast<const float4*>(Bptr + k0);
            if (!bval) pb = make_float4(0.f, 0.f, 0.f, 0.f);
        }
        #pragma unroll
        for (int kk = 0; kk < 16; kk++) {
            float4 av0 = *reinterpret_cast<const float4*>(&sA[buf][kk][ty*8]);
            float4 av1 = *reinterpret_cast<const float4*>(&sA[buf][kk][ty*8+4]);
            float4 bv  = *reinterpret_cast<const float4*>(&sB[buf][kk][tx*4]);
            float a[8] = {av0.x, av0.y, av0.z, av0.w, av1.x, av1.y, av1.z, av1.w};
            float b[4] = {bv.x, bv.y, bv.z, bv.w};
            #pragma unroll
            for (int i = 0; i < 8; i++)
                #pragma unroll
                for (int j = 0; j < 4; j++) acc[i][j] += a[i] * b[j];
        }
        if (has_next) {
            const int nb = buf ^ 1;
            sA[nb][lc+0][lr]    = pa0.x; sA[nb][lc+1][lr]    = pa0.y;
            sA[nb][lc+2][lr]    = pa0.z; sA[nb][lc+3][lr]    = pa0.w;
            sA[nb][lc+0][64+lr] = pa1.x; sA[nb][lc+1][64+lr] = pa1.y;
            sA[nb][lc+2][64+lr] = pa1.z; sA[nb][lc+3][64+lr] = pa1.w;
            sB[nb][lc+0][lr] = pb.x; sB[nb][lc+1][lr] = pb.y;
            sB[nb][lc+2][lr] = pb.z; sB[nb][lc+3][lr] = pb.w;
            __syncthreads();
            buf = nb;
        }
    }

    #pragma unroll
    for (int i = 0; i < 8; i++) {
        const int gm = row0 + ty*8 + i;
        #pragma unroll
        for (int j = 0; j < 4; j++) {
            int gn = col0 + tx*4 + j;
            if (gn < N)
                C[(size_t)gm * ldc + gn] = acc[i][j] + (bias ? bias[gn] : 0.f);
        }
    }
}

// ---------------- small generic GEMM (decoder init only) -------------------
__global__ void gemm32t(const float* __restrict__ A, int lda,
                        const float* __restrict__ Bm, int ldb,
                        float* __restrict__ C, int ldc,
                        const float* __restrict__ bias,
                        int M, int N, int K)
{
    __shared__ float sA[32][33];
    __shared__ float sB[32][33];
    const int tid = threadIdx.x;
    const int tx = tid & 15, ty = tid >> 4;
    const int row0 = blockIdx.y * 32, col0 = blockIdx.x * 32;

    float acc[2][2] = {{0,0},{0,0}};
    for (int k0 = 0; k0 < K; k0 += 32) {
        #pragma unroll
        for (int i = tid; i < 1024; i += 256) {
            int m = i >> 5, kk = i & 31;
            sA[kk][m] = A[(size_t)(row0 + m) * lda + k0 + kk];
            sB[kk][m] = Bm[(size_t)(col0 + m) * ldb + k0 + kk];
        }
        __syncthreads();
        #pragma unroll
        for (int kk = 0; kk < 32; kk++) {
            float a0 = sA[kk][ty*2], a1 = sA[kk][ty*2+1];
            float b0 = sB[kk][tx*2], b1 = sB[kk][tx*2+1];
            acc[0][0] += a0*b0; acc[0][1] += a0*b1;
            acc[1][0] += a1*b0; acc[1][1] += a1*b1;
        }
        __syncthreads();
    }
    #pragma unroll
    for (int i = 0; i < 2; i++)
        #pragma unroll
        for (int j = 0; j < 2; j++) {
            int gm = row0 + ty*2 + i, gn = col0 + tx*2 + j;
            C[(size_t)gm * ldc + gn] = tanhf(acc[i][j] + bias[gn]);
        }
}

// =====================================================================
//  Encoder fused step
// =====================================================================
__global__ __launch_bounds__(256)
void enc_step_kernel(const float* __restrict__ hf_in,  const float* __restrict__ hb_in,
                     float* __restrict__ hf_out, float* __restrict__ hb_out,
                     const float* __restrict__ Whh_f, const float* __restrict__ Whh_b,
                     const float* __restrict__ bhh_f, const float* __restrict__ bhh_b,
                     const float* __restrict__ xpf,   const float* __restrict__ xpb,
                     float* __restrict__ enc_out, int t)
{
    const int dir = blockIdx.z;
    const float* hin  = dir ? hb_in  : hf_in;
    const float* Whh  = dir ? Whh_b  : Whh_f;
    const float* bhh  = dir ? bhh_b  : bhh_f;
    const float* xp   = dir ? xpb    : xpf;
    float*       hout = dir ? hb_out : hf_out;
    const int s = dir ? (Ss - 1 - t) : t;

    const int j0 = blockIdx.x * 32, b0 = blockIdx.y * 32;
    const int tid = threadIdx.x;
    const int tx = tid & 15, ty = tid >> 4;

    __shared__ float sH[16][33];
    __shared__ float sW[3][16][34];

    float acc[2][2][3];
    #pragma unroll
    for (int bi = 0; bi < 2; bi++)
        #pragma unroll
        for (int ji = 0; ji < 2; ji++)
            #pragma unroll
            for (int g = 0; g < 3; g++) acc[bi][ji][g] = 0.f;

    for (int k0 = 0; k0 < Hh; k0 += 16) {
        #pragma unroll
        for (int i = tid; i < 512; i += 256) {
            int b = i >> 4, kk = i & 15;
            sH[kk][b] = hin[(size_t)(b0 + b) * Hh + k0 + kk];
        }
        #pragma unroll
        for (int i = tid; i < 1536; i += 256) {
            int r = i >> 4, kk = i & 15;
            int g = r / 32, j = r % 32;
            sW[g][kk][j] = Whh[(size_t)(g * Hh + j0 + j) * Hh + k0 + kk];
        }
        __syncthreads();
        #pragma unroll
        for (int kk = 0; kk < 16; kk++) {
            float hv[2] = { sH[kk][ty*2], sH[kk][ty*2 + 1] };
            #pragma unroll
            for (int g = 0; g < 3; g++) {
                float w0 = sW[g][kk][tx*2], w1 = sW[g][kk][tx*2 + 1];
                acc[0][0][g] += hv[0] * w0;
                acc[0][1][g] += hv[0] * w1;
                acc[1][0][g] += hv[1] * w0;
                acc[1][1][g] += hv[1] * w1;
            }
        }
        __syncthreads();
    }

    #pragma unroll
    for (int bi = 0; bi < 2; bi++) {
        int b = b0 + ty*2 + bi;
        #pragma unroll
        for (int ji = 0; ji < 2; ji++) {
            int j = j0 + tx*2 + ji;
            float rh = acc[bi][ji][0] + bhh[j];
            float zh = acc[bi][ji][1] + bhh[Hh + j];
            float nh = acc[bi][ji][2] + bhh[2*Hh + j];
            const float* x = xp + ((size_t)b * Ss + s) * (3*Hh);
            float r = sigf(x[j] + rh);
            float z = sigf(x[Hh + j] + zh);
            float n = tanhf(x[2*Hh + j] + r * nh);
            float hv = hin[(size_t)b * Hh + j];
            float hn = (1.f - z) * n + z * hv;
            hout[(size_t)b * Hh + j] = hn;
            enc_out[((size_t)b * Ss + s) * (2*Hh) + dir * Hh + j] = hn;
        }
    }
}

// =====================================================================
//  Decoder fused GRU step
// =====================================================================
__global__ __launch_bounds__(256)
void dec_fused_kernel(const float* __restrict__ rnin,
                      const float* __restrict__ hid_in,
                      const float* __restrict__ dec_Wih,
                      const float* __restrict__ dec_Whh,
                      const float* __restrict__ dec_bih,
                      const float* __restrict__ dec_bhh,
                      float* __restrict__ hid_out, float* __restrict__ cat,
                      unsigned long long* __restrict__ slots)
{
    const int j0 = blockIdx.x * 32, b0 = blockIdx.y * 32;
    const int tid = threadIdx.x;
    const int tx = tid & 15, ty = tid >> 4;

    __shared__ float sH[16][33];
    __shared__ float sW[4][16][34];

    float acc[2][2][4];
    #pragma unroll
    for (int bi = 0; bi < 2; bi++)
        #pragma unroll
        for (int ji = 0; ji < 2; ji++)
            #pragma unroll
            for (int g = 0; g < 4; g++) acc[bi][ji][g] = 0.f;

    for (int k0 = 0; k0 < RNK + Dd; k0 += 16) {
        const bool ih = (k0 < RNK);
        #pragma unroll
        for (int i = tid; i < 512; i += 256) {
            int b = i >> 4, kk = i & 15;
            sH[kk][b] = ih ? rnin[(size_t)(b0 + b) * RNK + k0 + kk]
                           : hid_in[(size_t)(b0 + b) * Dd + (k0 - RNK) + kk];
        }
        #pragma unroll
        for (int i = tid; i < 2048; i += 256) {
            int g = i >> 9;
            int r = (i >> 4) & 31;
            int kk = i & 15;
            int j = j0 + r;
            float w;
            if (ih) {
                w = (g == 3) ? 0.f
                    : dec_Wih[(size_t)(g * Dd + j) * RNK + k0 + kk];
            } else {
                w = (g == 2) ? 0.f
                    : dec_Whh[(size_t)(((g == 3) ? 2 : g) * Dd + j) * Dd + (k0 - RNK) + kk];
            }
            sW[g][kk][r] = w;
        }
        __syncthreads();
        #pragma unroll
        for (int kk = 0; kk < 16; kk++) {
            float hv0 = sH[kk][ty*2], hv1 = sH[kk][ty*2 + 1];
            #pragma unroll
            for (int g = 0; g < 4; g++) {
                float w0 = sW[g][kk][tx*2], w1 = sW[g][kk][tx*2 + 1];
                acc[0][0][g] += hv0 * w0;
                acc[0][1][g] += hv0 * w1;
                acc[1][0][g] += hv1 * w0;
                acc[1][1][g] += hv1 * w1;
            }
        }
        __syncthreads();
    }

    #pragma unroll
    for (int bi = 0; bi < 2; bi++) {
        int b = b0 + ty*2 + bi;
        #pragma unroll
        for (int ji = 0; ji < 2; ji++) {
            int j = j0 + tx*2 + ji;
            float r = sigf(acc[bi][ji][0] + dec_bih[j] + dec_bhh[j]);
            float z = sigf(acc[bi][ji][1] + dec_bih[Dd + j] + dec_bhh[Dd + j]);
            float n = tanhf(acc[bi][ji][2] + dec_bih[2*Dd + j]
                            + r * (acc[bi][ji][3] + dec_bhh[2*Dd + j]));
            float hv = hid_in[(size_t)b * Dd + j];
            float hn = (1.f - z) * n + z * hv;
            hid_out[(size_t)b * Dd + j] = hn;
            cat[(size_t)b * CAT + j] = hn;
            if (j == 0) slots[b] = 0ull;
        }
    }
}

// ---------------- small helper kernels ------------------------------------
__global__ void init0_kernel(float* hf, float* hb, unsigned long long* slots)
{
    int i = blockIdx.x * 256 + threadIdx.x;
    if (i < Bb * Hh) { hf[i] = 0.f; hb[i] = 0.f; }
    if (i < Bb)
        slots[i] = ((unsigned long long)fmono(0.f) << 32) | 0xFFFFFFFFull;
}

__global__ void embed_kernel(const int* __restrict__ inp,
                             const float* __restrict__ tab,
                             float* __restrict__ emb)
{
    int bs = blockIdx.x, j = threadIdx.x;
    int tk = inp[bs * 2 + 0];
    float m = (float)inp[bs * 2 + 1];
    emb[(size_t)bs * Ee + j] = tab[(size_t)tk * Ee + j] * m;
}

__global__ void transpose_attw_kernel(const float* __restrict__ attn_W,
                                      float* __restrict__ attWT)
{
    int k = blockIdx.x, j = threadIdx.x;
    attWT[(size_t)k * Aa + j] = attn_W[(size_t)j * (Dd + 2*Hh) + k];
}

__global__ void concat_fc_kernel(const float* __restrict__ hf,
                                 const float* __restrict__ hb,
                                 float* __restrict__ fcin)
{
    int b = blockIdx.x, j = threadIdx.x;
    fcin[(size_t)b*2*Hh + j]      = hf[(size_t)b*Hh + j];
    fcin[(size_t)b*2*Hh + Hh + j] = hb[(size_t)b*Hh + j];
}

// attention (with fused hproj) + decoder-token embedding
__global__ __launch_bounds__(256)
void attn_embed_kernel(const float* __restrict__ encp,
                       const float* __restrict__ hid,
                       const float* __restrict__ attWT,
                       const float* __restrict__ enc_out,
                       const unsigned long long* __restrict__ slots,
                       const float* __restrict__ tab,
                       float* __restrict__ rnin, float* __restrict__ cat)
{
    int b = blockIdx.x, tid = threadIdx.x;
    int lane = tid & 31, w = tid >> 5;
    __shared__ float shid[Dd];
    __shared__ float shp[Aa];
    __shared__ float salpha[Ss];

    shid[tid] = hid[(size_t)b*Dd + tid];
    __syncthreads();

    float hp = 0.f;
    #pragma unroll 8
    for (int k = 0; k < Dd; k++) hp += shid[k] * attWT[(size_t)k * Aa + tid];
    shp[tid] = hp;
    __syncthreads();

    #pragma unroll
    for (int i = 0; i < 8; i++) {
        int s = w + 8 * i;
        const float* row = encp + ((size_t)b*Ss + s)*Aa;
        float acc = 0.f;
        #pragma unroll
        for (int a = lane; a < Aa; a += 32) acc += tanhf(row[a] + shp[a]);
        #pragma unroll
        for (int o = 16; o; o >>= 1) acc += __shfl_xor_sync(0xffffffffu, acc, o);
        if (lane == 0) salpha[s] = acc;
    }
    __syncthreads();
    if (w == 0) {
        float v0 = salpha[lane], v1 = salpha[lane + 32];
        float m = fmaxf(v0, v1);
        #pragma unroll
        for (int o = 16; o; o >>= 1) m = fmaxf(m, __shfl_xor_sync(0xffffffffu, m, o));
        float e0 = expf(v0 - m), e1 = expf(v1 - m);
        float sum = e0 + e1;
        #pragma unroll
        for (int o = 16; o; o >>= 1) sum += __shfl_xor_sync(0xffffffffu, sum, o);
        float inv = 1.f / sum;
        salpha[lane] = e0 * inv; salpha[lane + 32] = e1 * inv;
    }
    __syncthreads();
    float a0 = 0.f, a1 = 0.f;
    for (int s = 0; s < Ss; s++) {
        float al = salpha[s];
        const float* eo = enc_out + ((size_t)b*Ss + s)*(2*Hh);
        a0 += al * eo[tid];
        a1 += al * eo[Hh + tid];
    }
    rnin[(size_t)b*RNK + Ee + tid]      = a0;
    rnin[(size_t)b*RNK + Ee + Hh + tid] = a1;
    cat[(size_t)b*CAT + Dd + tid]       = a0;
    cat[(size_t)b*CAT + Dd + Hh + tid]  = a1;

    int tk = (int)(0xFFFFFFFFu - (unsigned)(slots[b] & 0xFFFFFFFFull));
    float e = tab[(size_t)tk * Ee + tid];
    rnin[(size_t)b*RNK + tid] = e;
    cat[(size_t)b*CAT + Dd + 2*Hh + tid] = e;
}

__global__ void logsoftmax_kernel(float* __restrict__ out)
{
    int row = blockIdx.x, tid = threadIdx.x;
    int s = row & (Ss - 1);
    float* p = out + (size_t)row * Vv;
    if (s == 0) {
        float L = logf(expf(1.f) + (float)(Vv - 1));
        for (int v = tid; v < Vv; v += 256) p[v] = (v == 0 ? 1.f : 0.f) - L;
        return;
    }
    constexpr int PT = (Vv + 255) / 256;
    float regs[PT];
    float m = -INFINITY;
    #pragma unroll
    for (int i = 0; i < PT; i++) {
        int v = tid + i * 256;
        if (v < Vv) { regs[i] = p[v]; m = fmaxf(m, regs[i]); }
        else regs[i] = -INFINITY;
    }
    __shared__ float sm[256];
    sm[tid] = m; __syncthreads();
    for (int o = 128; o; o >>= 1) { if (tid < o) sm[tid] = fmaxf(sm[tid], sm[tid+o]); __syncthreads(); }
    m = sm[0]; __syncthreads();
    float sum = 0.f;
    #pragma unroll
    for (int i = 0; i < PT; i++) {
        int v = tid + i * 256;
        if (v < Vv) sum += expf(regs[i] - m);
    }
    sm[tid] = sum; __syncthreads();
    for (int o = 128; o; o >>= 1) { if (tid < o) sm[tid] += sm[tid+o]; __syncthreads(); }
    float ls = m + logf(sm[0]);
    #pragma unroll
    for (int i = 0; i < PT; i++) {
        int v = tid + i * 256;
        if (v < Vv) p[v] = regs[i] - ls;
    }
}

// ---------------- launch helpers ------------------------------------------
static inline dim3 gridL(int M, int N) { return dim3((N + 63) / 64, M / 128); }
static inline dim3 grid88(int M, int N) { return dim3((N + 63) / 64, M / 64); }

extern "C" void kernel_launch(void* const* d_in, const int* in_sizes, int n_in,
                              void* d_out, int out_size)
{
    const int*   inp       = (const int*)  d_in[0];
    const float* emb_table = (const float*)d_in[1];
    const float* Wih_f     = (const float*)d_in[2];
    const float* Whh_f     = (const float*)d_in[3];
    const float* bih_f     = (const float*)d_in[4];
    const float* bhh_f     = (const float*)d_in[5];
    const float* Wih_b     = (const float*)d_in[6];
    const float* Whh_b     = (const float*)d_in[7];
    const float* bih_b     = (const float*)d_in[8];
    const float* bhh_b     = (const float*)d_in[9];
    const float* fc_W      = (const float*)d_in[10];
    const float* fc_b      = (const float*)d_in[11];
    const float* attn_W    = (const float*)d_in[12];
    const float* attn_b    = (const float*)d_in[13];
    const float* dec_Wih   = (const float*)d_in[14];
    const float* dec_Whh   = (const float*)d_in[15];
    const float* dec_bih   = (const float*)d_in[16];
    const float* dec_bhh   = (const float*)d_in[17];
    const float* out_W     = (const float*)d_in[18];
    const float* out_b     = (const float*)d_in[19];
    float* out = (float*)d_out;

    float* scr = nullptr;
    cudaGetSymbolAddress((void**)&scr, g_scratch);
    float* emb   = scr + OFF_EMB;
    float* xpf   = scr + OFF_XPF;
    float* xpb   = scr + OFF_XPB;
    float* enco  = scr + OFF_ENCO;
    float* encp  = scr + OFF_ENCP;
    float* hf0   = scr + OFF_HF0;
    float* hf1   = scr + OFF_HF1;
    float* hb0   = scr + OFF_HB0;
    float* hb1   = scr + OFF_HB1;
    float* hid0  = scr + OFF_HID0;
    float* hid1  = scr + OFF_HID1;
    float* fcin  = scr + OFF_FCIN;
    float* rnin  = scr + OFF_RNIN;
    float* cat   = scr + OFF_CAT;
    float* attWT = scr + OFF_ATTWT;
    unsigned long long* slots = (unsigned long long*)(scr + OFF_SLOT);

    // ---- init + embedding + one-time GEMMs ----
    init0_kernel<<<(Bb*Hh + 255)/256, 256>>>(hf0, hb0, slots);
    embed_kernel<<<Bb*Ss, 256>>>(inp, emb_table, emb);
    transpose_attw_kernel<<<Dd, Aa>>>(attn_W, attWT);
    gemmL<<<gridL(Bb*Ss, 3*Hh), 256>>>(emb, Ee, Wih_f, Ee, xpf, 3*Hh, bih_f, Bb*Ss, 3*Hh, Ee);
    gemmL<<<gridL(Bb*Ss, 3*Hh), 256>>>(emb, Ee, Wih_b, Ee, xpb, 3*Hh, bih_b, Bb*Ss, 3*Hh, Ee);

    // ---- encoder recurrence ----
    for (int t = 0; t < Ss; t++) {
        const float* hfi = (t & 1) ? hf1 : hf0;
        const float* hbi = (t & 1) ? hb1 : hb0;
        float* hfo = (t & 1) ? hf0 : hf1;
        float* hbo = (t & 1) ? hb0 : hb1;
        enc_step_kernel<<<dim3(8, 4, 2), 256>>>(hfi, hbi, hfo, hbo,
                                                Whh_f, Whh_b, bhh_f, bhh_b,
                                                xpf, xpb, enco, t);
    }

    // ---- decoder init ----
    concat_fc_kernel<<<Bb, 256>>>(hf0, hb0, fcin);
    gemm32t<<<dim3(Dd/32, Bb/32), 256>>>(fcin, 2*Hh, fc_W, 2*Hh, hid0, Dd, fc_b, Bb, Dd, 2*Hh);

    // ---- attention projection of enc_out (one-time) ----
    gemmL<<<gridL(Bb*Ss, Aa), 256>>>(enco, 2*Hh, attn_W + Dd, Dd + 2*Hh, encp, Aa, attn_b, Bb*Ss, Aa, 2*Hh);

    // ---- decoder steps (3 launches each) ----
    for (int t = 0; t < Ss - 1; t++) {
        const float* hin = (t & 1) ? hid1 : hid0;
        float*       hout = (t & 1) ? hid0 : hid1;
        attn_embed_kernel<<<Bb, 256>>>(encp, hin, attWT, enco, slots, emb_table, rnin, cat);
        dec_fused_kernel<<<dim3(8, 4), 256>>>(rnin, hin, dec_Wih, dec_Whh,
                                              dec_bih, dec_bhh, hout, cat, slots);
        gemm88<1><<<grid88(Bb, Vv), 64>>>(cat, CAT, out_W, CAT,
                                          out + (size_t)(t + 1) * Vv, Ss * Vv, out_b,
                                          Bb, Vv, CAT, slots);
    }

    // ---- final log-softmax ----
    logsoftmax_kernel<<<Bb*Ss, 256>>>(out);
}

// round 6
// speedup vs baseline: 1.1790x; 1.1790x over previous
#include <cuda_runtime.h>
#include <math.h>
#include <stdint.h>

// Problem dims
constexpr int Bb = 128, Ss = 64, Ee = 256, Hh = 256, Dd = 256, Aa = 256, Vv = 10000;
constexpr int CAT = Dd + 2*Hh + Ee;   // 1024
constexpr int RNK = Ee + 2*Hh;        // 768

// ---------------- scratch ---------------------------------------------------
constexpr size_t OFF_EMB   = 0;
constexpr size_t OFF_XPF   = OFF_EMB   + (size_t)Bb*Ss*Ee;
constexpr size_t OFF_XPB   = OFF_XPF   + (size_t)Bb*Ss*3*Hh;
constexpr size_t OFF_ENCO  = OFF_XPB   + (size_t)Bb*Ss*3*Hh;
constexpr size_t OFF_ENCP  = OFF_ENCO  + (size_t)Bb*Ss*2*Hh;
constexpr size_t OFF_HF0   = OFF_ENCP  + (size_t)Bb*Ss*Aa;
constexpr size_t OFF_HF1   = OFF_HF0   + (size_t)Bb*Hh;
constexpr size_t OFF_HB0   = OFF_HF1   + (size_t)Bb*Hh;
constexpr size_t OFF_HB1   = OFF_HB0   + (size_t)Bb*Hh;
constexpr size_t OFF_HID0  = OFF_HB1   + (size_t)Bb*Hh;
constexpr size_t OFF_HID1  = OFF_HID0  + (size_t)Bb*Dd;
constexpr size_t OFF_FCIN  = OFF_HID1  + (size_t)Bb*Dd;
constexpr size_t OFF_RNIN  = OFF_FCIN  + (size_t)Bb*2*Hh;
constexpr size_t OFF_CAT   = OFF_RNIN  + (size_t)Bb*RNK;
constexpr size_t OFF_ATTWT = OFF_CAT   + (size_t)Bb*CAT;
constexpr size_t OFF_SLOT  = OFF_ATTWT + (size_t)Dd*Aa;
constexpr size_t SCR_TOTAL = OFF_SLOT  + (size_t)2*Bb;

__device__ __align__(256) float g_scratch[SCR_TOTAL];

__device__ __forceinline__ float sigf(float x) { return 1.f / (1.f + expf(-x)); }

__device__ __forceinline__ unsigned int fmono(float x) {
    unsigned int b = __float_as_uint(x);
    return (b & 0x80000000u) ? ~b : (b | 0x80000000u);
}

// =====================================================================
//  gemmSK: logits GEMM. C[M,N] = A[M,K] @ B[N,K]^T + bias, fused argmax.
//  BM=64, BN=64, BK=16, TM=8, TN=8. 128 threads = 2 groups of 64;
//  group kg computes kk = kg*8 .. kg*8+7 of each chunk over SHARED
//  smem buffers (LDS:FMA = 0.25, 4 warps/block). Partial sums reduced
//  through smem at the end (group 1 -> smem, group 0 adds + epilogue).
//  Requires M%64==0, K%16==0, lda%4==0, ldb%4==0, 16B-aligned bases.
// =====================================================================
__global__ __launch_bounds__(128)
void gemmSK(const float* __restrict__ A, int lda,
            const float* __restrict__ Bm, int ldb,
            float* __restrict__ C, int ldc,
            const float* __restrict__ bias,
            int M, int N, int K,
            unsigned long long* __restrict__ slots)
{
    // sA: [2][16][68] floats at sm[0..2175], sB at sm[2176..4351]
    // epilogue reduction buffer (4096 floats) aliases the same storage.
    __shared__ __align__(16) float sm[4352];
    float* sAb = sm;
    float* sBb = sm + 2176;

    const int tid = threadIdx.x;
    const int kg  = tid >> 6;          // k-group: 0 or 1
    const int t64 = tid & 63;
    const int tx = t64 & 7, ty = t64 >> 3;
    const int row0 = blockIdx.y * 64, col0 = blockIdx.x * 64;

    // cooperative loads: 256 float4 per tile (A and B each); thread does 2+2.
    const int i0 = tid, i1 = tid + 128;
    const int ar0 = i0 >> 2, ac0 = (i0 & 3) * 4;
    const int ar1 = i1 >> 2, ac1 = (i1 & 3) * 4;

    const float* Ap0 = A + (size_t)(row0 + ar0) * lda + ac0;
    const float* Ap1 = A + (size_t)(row0 + ar1) * lda + ac1;
    const int bn0 = col0 + ar0, bn1 = col0 + ar1;
    const bool bv0 = (bn0 < N), bv1 = (bn1 < N);
    const float* Bp0 = Bm + (size_t)(bv0 ? bn0 : N - 1) * ldb + ac0;
    const float* Bp1 = Bm + (size_t)(bv1 ? bn1 : N - 1) * ldb + ac1;

    float4 pa0 = *reinterpret_cast<const float4*>(Ap0);
    float4 pa1 = *reinterpret_cast<const float4*>(Ap1);
    float4 pb0 = bv0 ? *reinterpret_cast<const float4*>(Bp0) : make_float4(0,0,0,0);
    float4 pb1 = bv1 ? *reinterpret_cast<const float4*>(Bp1) : make_float4(0,0,0,0);

    {
        float* a0 = sAb + 0*1088; float* b0 = sBb + 0*1088;
        a0[(ac0+0)*68 + ar0] = pa0.x; a0[(ac0+1)*68 + ar0] = pa0.y;
        a0[(ac0+2)*68 + ar0] = pa0.z; a0[(ac0+3)*68 + ar0] = pa0.w;
        a0[(ac1+0)*68 + ar1] = pa1.x; a0[(ac1+1)*68 + ar1] = pa1.y;
        a0[(ac1+2)*68 + ar1] = pa1.z; a0[(ac1+3)*68 + ar1] = pa1.w;
        b0[(ac0+0)*68 + ar0] = pb0.x; b0[(ac0+1)*68 + ar0] = pb0.y;
        b0[(ac0+2)*68 + ar0] = pb0.z; b0[(ac0+3)*68 + ar0] = pb0.w;
        b0[(ac1+0)*68 + ar1] = pb1.x; b0[(ac1+1)*68 + ar1] = pb1.y;
        b0[(ac1+2)*68 + ar1] = pb1.z; b0[(ac1+3)*68 + ar1] = pb1.w;
    }
    __syncthreads();

    float acc[8][8];
    #pragma unroll
    for (int i = 0; i < 8; i++)
        #pragma unroll
        for (int j = 0; j < 8; j++) acc[i][j] = 0.f;

    int buf = 0;
    for (int k0 = 16; k0 <= K; k0 += 16) {
        const bool has_next = (k0 < K);
        if (has_next) {
            pa0 = *reinterpret_cast<const float4*>(Ap0 + k0);
            pa1 = *reinterpret_cast<const float4*>(Ap1 + k0);
            pb0 = bv0 ? *reinterpret_cast<const float4*>(Bp0 + k0) : make_float4(0,0,0,0);
            pb1 = bv1 ? *reinterpret_cast<const float4*>(Bp1 + k0) : make_float4(0,0,0,0);
        }
        const float* aB = sAb + buf*1088 + kg*8*68;
        const float* bB = sBb + buf*1088 + kg*8*68;
        #pragma unroll
        for (int q = 0; q < 8; q++) {
            float4 av0 = *reinterpret_cast<const float4*>(aB + q*68 + ty*8);
            float4 av1 = *reinterpret_cast<const float4*>(aB + q*68 + ty*8 + 4);
            float4 bv0_ = *reinterpret_cast<const float4*>(bB + q*68 + tx*8);
            float4 bv1_ = *reinterpret_cast<const float4*>(bB + q*68 + tx*8 + 4);
            float a[8] = {av0.x, av0.y, av0.z, av0.w, av1.x, av1.y, av1.z, av1.w};
            float b[8] = {bv0_.x, bv0_.y, bv0_.z, bv0_.w, bv1_.x, bv1_.y, bv1_.z, bv1_.w};
            #pragma unroll
            for (int i = 0; i < 8; i++)
                #pragma unroll
                for (int j = 0; j < 8; j++) acc[i][j] += a[i] * b[j];
        }
        if (has_next) {
            const int nb = buf ^ 1;
            float* an = sAb + nb*1088; float* bn = sBb + nb*1088;
            __syncthreads();   // previous buf fully consumed before overwrite
            an[(ac0+0)*68 + ar0] = pa0.x; an[(ac0+1)*68 + ar0] = pa0.y;
            an[(ac0+2)*68 + ar0] = pa0.z; an[(ac0+3)*68 + ar0] = pa0.w;
            an[(ac1+0)*68 + ar1] = pa1.x; an[(ac1+1)*68 + ar1] = pa1.y;
            an[(ac1+2)*68 + ar1] = pa1.z; an[(ac1+3)*68 + ar1] = pa1.w;
            bn[(ac0+0)*68 + ar0] = pb0.x; bn[(ac0+1)*68 + ar0] = pb0.y;
            bn[(ac0+2)*68 + ar0] = pb0.z; bn[(ac0+3)*68 + ar0] = pb0.w;
            bn[(ac1+0)*68 + ar1] = pb1.x; bn[(ac1+1)*68 + ar1] = pb1.y;
            bn[(ac1+2)*68 + ar1] = pb1.z; bn[(ac1+3)*68 + ar1] = pb1.w;
            __syncthreads();
            buf = nb;
        }
    }
    __syncthreads();   // done with tile buffers; alias as reduction buffer

    // group 1 -> smem partials
    if (kg == 1) {
        #pragma unroll
        for (int i = 0; i < 8; i++) {
            float* r = sm + (ty*8 + i) * 64 + tx*8;
            *reinterpret_cast<float4*>(r)     = make_float4(acc[i][0], acc[i][1], acc[i][2], acc[i][3]);
            *reinterpret_cast<float4*>(r + 4) = make_float4(acc[i][4], acc[i][5], acc[i][6], acc[i][7]);
        }
    }
    __syncthreads();

    if (kg == 0) {
        float bb[8];
        #pragma unroll
        for (int j = 0; j < 8; j++) {
            int gn = col0 + tx*8 + j;
            bb[j] = (bias && gn < N) ? bias[gn] : 0.f;
        }
        #pragma unroll
        for (int i = 0; i < 8; i++) {
            const int gm = row0 + ty*8 + i;
            const float* r = sm + (ty*8 + i) * 64 + tx*8;
            float bestv = -INFINITY; int besti = 0;
            #pragma unroll
            for (int j = 0; j < 8; j++) {
                int gn = col0 + tx*8 + j;
                if (gn < N) {
                    float v = acc[i][j] + r[j] + bb[j];
                    C[(size_t)gm * ldc + gn] = v;
                    if (v > bestv) { bestv = v; besti = gn; }
                }
            }
            unsigned long long key =
                ((unsigned long long)fmono(bestv) << 32) |
                (unsigned long long)(0xFFFFFFFFu - (unsigned)besti);
            #pragma unroll
            for (int o = 4; o; o >>= 1) {
                unsigned long long ok = __shfl_xor_sync(0xffffffffu, key, o);
                if (ok > key) key = ok;
            }
            if (tx == 0) atomicMax(&slots[gm], key);
        }
    }
}

// =====================================================================
//  gemmL: big one-time GEMMs (unchanged, passing).
// =====================================================================
__global__ __launch_bounds__(256)
void gemmL(const float* __restrict__ A, int lda,
           const float* __restrict__ Bm, int ldb,
           float* __restrict__ C, int ldc,
           const float* __restrict__ bias,
           int M, int N, int K)
{
    __shared__ __align__(16) float sA[2][16][132];
    __shared__ __align__(16) float sB[2][16][68];
    const int tid = threadIdx.x;
    const int tx = tid & 15, ty = tid >> 4;
    const int row0 = blockIdx.y * 128, col0 = blockIdx.x * 64;
    const int lr = tid >> 2;
    const int lc = (tid & 3) * 4;

    const float* Aptr0 = A + (size_t)(row0 + lr) * lda + lc;
    const float* Aptr1 = A + (size_t)(row0 + 64 + lr) * lda + lc;
    const int gnl = col0 + lr;
    const int gnc = (gnl < N) ? gnl : (N - 1);
    const float* Bptr = Bm + (size_t)gnc * ldb + lc;
    const bool bval = (gnl < N);

    float4 pa0 = *reinterpret_cast<const float4*>(Aptr0);
    float4 pa1 = *reinterpret_cast<const float4*>(Aptr1);
    float4 pb  = *reinterpret_cast<const float4*>(Bptr);
    if (!bval) pb = make_float4(0.f, 0.f, 0.f, 0.f);

    sA[0][lc+0][lr]    = pa0.x; sA[0][lc+1][lr]    = pa0.y;
    sA[0][lc+2][lr]    = pa0.z; sA[0][lc+3][lr]    = pa0.w;
    sA[0][lc+0][64+lr] = pa1.x; sA[0][lc+1][64+lr] = pa1.y;
    sA[0][lc+2][64+lr] = pa1.z; sA[0][lc+3][64+lr] = pa1.w;
    sB[0][lc+0][lr] = pb.x; sB[0][lc+1][lr] = pb.y;
    sB[0][lc+2][lr] = pb.z; sB[0][lc+3][lr] = pb.w;
    __syncthreads();

    float acc[8][4];
    #pragma unroll
    for (int i = 0; i < 8; i++)
        #pragma unroll
        for (int j = 0; j < 4; j++) acc[i][j] = 0.f;

    int buf = 0;
    for (int k0 = 16; k0 <= K; k0 += 16) {
        const bool has_next = (k0 < K);
        if (has_next) {
            pa0 = *reinterpret_cast<const float4*>(Aptr0 + k0);
            pa1 = *reinterpret_cast<const float4*>(Aptr1 + k0);
            pb  = *reinterpret_cast<const float4*>(Bptr + k0);
            if (!bval) pb = make_float4(0.f, 0.f, 0.f, 0.f);
        }
        #pragma unroll
        for (int kk = 0; kk < 16; kk++) {
            float4 av0 = *reinterpret_cast<const float4*>(&sA[buf][kk][ty*8]);
            float4 av1 = *reinterpret_cast<const float4*>(&sA[buf][kk][ty*8+4]);
            float4 bv  = *reinterpret_cast<const float4*>(&sB[buf][kk][tx*4]);
            float a[8] = {av0.x, av0.y, av0.z, av0.w, av1.x, av1.y, av1.z, av1.w};
            float b[4] = {bv.x, bv.y, bv.z, bv.w};
            #pragma unroll
            for (int i = 0; i < 8; i++)
                #pragma unroll
                for (int j = 0; j < 4; j++) acc[i][j] += a[i] * b[j];
        }
        if (has_next) {
            const int nb = buf ^ 1;
            sA[nb][lc+0][lr]    = pa0.x; sA[nb][lc+1][lr]    = pa0.y;
            sA[nb][lc+2][lr]    = pa0.z; sA[nb][lc+3][lr]    = pa0.w;
            sA[nb][lc+0][64+lr] = pa1.x; sA[nb][lc+1][64+lr] = pa1.y;
            sA[nb][lc+2][64+lr] = pa1.z; sA[nb][lc+3][64+lr] = pa1.w;
            sB[nb][lc+0][lr] = pb.x; sB[nb][lc+1][lr] = pb.y;
            sB[nb][lc+2][lr] = pb.z; sB[nb][lc+3][lr] = pb.w;
            __syncthreads();
            buf = nb;
        }
    }

    #pragma unroll
    for (int i = 0; i < 8; i++) {
        const int gm = row0 + ty*8 + i;
        #pragma unroll
        for (int j = 0; j < 4; j++) {
            int gn = col0 + tx*4 + j;
            if (gn < N)
                C[(size_t)gm * ldc + gn] = acc[i][j] + (bias ? bias[gn] : 0.f);
        }
    }
}

// ---------------- small generic GEMM (decoder init only) -------------------
__global__ void gemm32t(const float* __restrict__ A, int lda,
                        const float* __restrict__ Bm, int ldb,
                        float* __restrict__ C, int ldc,
                        const float* __restrict__ bias,
                        int M, int N, int K)
{
    __shared__ float sA[32][33];
    __shared__ float sB[32][33];
    const int tid = threadIdx.x;
    const int tx = tid & 15, ty = tid >> 4;
    const int row0 = blockIdx.y * 32, col0 = blockIdx.x * 32;

    float acc[2][2] = {{0,0},{0,0}};
    for (int k0 = 0; k0 < K; k0 += 32) {
        #pragma unroll
        for (int i = tid; i < 1024; i += 256) {
            int m = i >> 5, kk = i & 31;
            sA[kk][m] = A[(size_t)(row0 + m) * lda + k0 + kk];
            sB[kk][m] = Bm[(size_t)(col0 + m) * ldb + k0 + kk];
        }
        __syncthreads();
        #pragma unroll
        for (int kk = 0; kk < 32; kk++) {
            float a0 = sA[kk][ty*2], a1 = sA[kk][ty*2+1];
            float b0 = sB[kk][tx*2], b1 = sB[kk][tx*2+1];
            acc[0][0] += a0*b0; acc[0][1] += a0*b1;
            acc[1][0] += a1*b0; acc[1][1] += a1*b1;
        }
        __syncthreads();
    }
    #pragma unroll
    for (int i = 0; i < 2; i++)
        #pragma unroll
        for (int j = 0; j < 2; j++) {
            int gm = row0 + ty*2 + i, gn = col0 + tx*2 + j;
            C[(size_t)gm * ldc + gn] = tanhf(acc[i][j] + bias[gn]);
        }
}

// =====================================================================
//  Encoder fused step
// =====================================================================
__global__ __launch_bounds__(256)
void enc_step_kernel(const float* __restrict__ hf_in,  const float* __restrict__ hb_in,
                     float* __restrict__ hf_out, float* __restrict__ hb_out,
                     const float* __restrict__ Whh_f, const float* __restrict__ Whh_b,
                     const float* __restrict__ bhh_f, const float* __restrict__ bhh_b,
                     const float* __restrict__ xpf,   const float* __restrict__ xpb,
                     float* __restrict__ enc_out, int t)
{
    const int dir = blockIdx.z;
    const float* hin  = dir ? hb_in  : hf_in;
    const float* Whh  = dir ? Whh_b  : Whh_f;
    const float* bhh  = dir ? bhh_b  : bhh_f;
    const float* xp   = dir ? xpb    : xpf;
    float*       hout = dir ? hb_out : hf_out;
    const int s = dir ? (Ss - 1 - t) : t;

    const int j0 = blockIdx.x * 32, b0 = blockIdx.y * 32;
    const int tid = threadIdx.x;
    const int tx = tid & 15, ty = tid >> 4;

    __shared__ float sH[16][33];
    __shared__ float sW[3][16][34];

    float acc[2][2][3];
    #pragma unroll
    for (int bi = 0; bi < 2; bi++)
        #pragma unroll
        for (int ji = 0; ji < 2; ji++)
            #pragma unroll
            for (int g = 0; g < 3; g++) acc[bi][ji][g] = 0.f;

    for (int k0 = 0; k0 < Hh; k0 += 16) {
        #pragma unroll
        for (int i = tid; i < 512; i += 256) {
            int b = i >> 4, kk = i & 15;
            sH[kk][b] = hin[(size_t)(b0 + b) * Hh + k0 + kk];
        }
        #pragma unroll
        for (int i = tid; i < 1536; i += 256) {
            int r = i >> 4, kk = i & 15;
            int g = r / 32, j = r % 32;
            sW[g][kk][j] = Whh[(size_t)(g * Hh + j0 + j) * Hh + k0 + kk];
        }
        __syncthreads();
        #pragma unroll
        for (int kk = 0; kk < 16; kk++) {
            float hv[2] = { sH[kk][ty*2], sH[kk][ty*2 + 1] };
            #pragma unroll
            for (int g = 0; g < 3; g++) {
                float w0 = sW[g][kk][tx*2], w1 = sW[g][kk][tx*2 + 1];
                acc[0][0][g] += hv[0] * w0;
                acc[0][1][g] += hv[0] * w1;
                acc[1][0][g] += hv[1] * w0;
                acc[1][1][g] += hv[1] * w1;
            }
        }
        __syncthreads();
    }

    #pragma unroll
    for (int bi = 0; bi < 2; bi++) {
        int b = b0 + ty*2 + bi;
        #pragma unroll
        for (int ji = 0; ji < 2; ji++) {
            int j = j0 + tx*2 + ji;
            float rh = acc[bi][ji][0] + bhh[j];
            float zh = acc[bi][ji][1] + bhh[Hh + j];
            float nh = acc[bi][ji][2] + bhh[2*Hh + j];
            const float* x = xp + ((size_t)b * Ss + s) * (3*Hh);
            float r = sigf(x[j] + rh);
            float z = sigf(x[Hh + j] + zh);
            float n = tanhf(x[2*Hh + j] + r * nh);
            float hv = hin[(size_t)b * Hh + j];
            float hn = (1.f - z) * n + z * hv;
            hout[(size_t)b * Hh + j] = hn;
            enc_out[((size_t)b * Ss + s) * (2*Hh) + dir * Hh + j] = hn;
        }
    }
}

// =====================================================================
//  Decoder fused GRU step
// =====================================================================
__global__ __launch_bounds__(256)
void dec_fused_kernel(const float* __restrict__ rnin,
                      const float* __restrict__ hid_in,
                      const float* __restrict__ dec_Wih,
                      const float* __restrict__ dec_Whh,
                      const float* __restrict__ dec_bih,
                      const float* __restrict__ dec_bhh,
                      float* __restrict__ hid_out, float* __restrict__ cat,
                      unsigned long long* __restrict__ slots)
{
    const int j0 = blockIdx.x * 32, b0 = blockIdx.y * 32;
    const int tid = threadIdx.x;
    const int tx = tid & 15, ty = tid >> 4;

    __shared__ float sH[16][33];
    __shared__ float sW[4][16][34];

    float acc[2][2][4];
    #pragma unroll
    for (int bi = 0; bi < 2; bi++)
        #pragma unroll
        for (int ji = 0; ji < 2; ji++)
            #pragma unroll
            for (int g = 0; g < 4; g++) acc[bi][ji][g] = 0.f;

    for (int k0 = 0; k0 < RNK + Dd; k0 += 16) {
        const bool ih = (k0 < RNK);
        #pragma unroll
        for (int i = tid; i < 512; i += 256) {
            int b = i >> 4, kk = i & 15;
            sH[kk][b] = ih ? rnin[(size_t)(b0 + b) * RNK + k0 + kk]
                           : hid_in[(size_t)(b0 + b) * Dd + (k0 - RNK) + kk];
        }
        #pragma unroll
        for (int i = tid; i < 2048; i += 256) {
            int g = i >> 9;
            int r = (i >> 4) & 31;
            int kk = i & 15;
            int j = j0 + r;
            float w;
            if (ih) {
                w = (g == 3) ? 0.f
                    : dec_Wih[(size_t)(g * Dd + j) * RNK + k0 + kk];
            } else {
                w = (g == 2) ? 0.f
                    : dec_Whh[(size_t)(((g == 3) ? 2 : g) * Dd + j) * Dd + (k0 - RNK) + kk];
            }
            sW[g][kk][r] = w;
        }
        __syncthreads();
        #pragma unroll
        for (int kk = 0; kk < 16; kk++) {
            float hv0 = sH[kk][ty*2], hv1 = sH[kk][ty*2 + 1];
            #pragma unroll
            for (int g = 0; g < 4; g++) {
                float w0 = sW[g][kk][tx*2], w1 = sW[g][kk][tx*2 + 1];
                acc[0][0][g] += hv0 * w0;
                acc[0][1][g] += hv0 * w1;
                acc[1][0][g] += hv1 * w0;
                acc[1][1][g] += hv1 * w1;
            }
        }
        __syncthreads();
    }

    #pragma unroll
    for (int bi = 0; bi < 2; bi++) {
        int b = b0 + ty*2 + bi;
        #pragma unroll
        for (int ji = 0; ji < 2; ji++) {
            int j = j0 + tx*2 + ji;
            float r = sigf(acc[bi][ji][0] + dec_bih[j] + dec_bhh[j]);
            float z = sigf(acc[bi][ji][1] + dec_bih[Dd + j] + dec_bhh[Dd + j]);
            float n = tanhf(acc[bi][ji][2] + dec_bih[2*Dd + j]
                            + r * (acc[bi][ji][3] + dec_bhh[2*Dd + j]));
            float hv = hid_in[(size_t)b * Dd + j];
            float hn = (1.f - z) * n + z * hv;
            hid_out[(size_t)b * Dd + j] = hn;
            cat[(size_t)b * CAT + j] = hn;
            if (j == 0) slots[b] = 0ull;
        }
    }
}

// ---------------- small helper kernels ------------------------------------
__global__ void init0_kernel(float* hf, float* hb, unsigned long long* slots)
{
    int i = blockIdx.x * 256 + threadIdx.x;
    if (i < Bb * Hh) { hf[i] = 0.f; hb[i] = 0.f; }
    if (i < Bb)
        slots[i] = ((unsigned long long)fmono(0.f) << 32) | 0xFFFFFFFFull;
}

__global__ void embed_kernel(const int* __restrict__ inp,
                             const float* __restrict__ tab,
                             float* __restrict__ emb)
{
    int bs = blockIdx.x, j = threadIdx.x;
    int tk = inp[bs * 2 + 0];
    float m = (float)inp[bs * 2 + 1];
    emb[(size_t)bs * Ee + j] = tab[(size_t)tk * Ee + j] * m;
}

__global__ void transpose_attw_kernel(const float* __restrict__ attn_W,
                                      float* __restrict__ attWT)
{
    int k = blockIdx.x, j = threadIdx.x;
    attWT[(size_t)k * Aa + j] = attn_W[(size_t)j * (Dd + 2*Hh) + k];
}

__global__ void concat_fc_kernel(const float* __restrict__ hf,
                                 const float* __restrict__ hb,
                                 float* __restrict__ fcin)
{
    int b = blockIdx.x, j = threadIdx.x;
    fcin[(size_t)b*2*Hh + j]      = hf[(size_t)b*Hh + j];
    fcin[(size_t)b*2*Hh + Hh + j] = hb[(size_t)b*Hh + j];
}

// attention (with fused hproj) + decoder-token embedding
__global__ __launch_bounds__(256)
void attn_embed_kernel(const float* __restrict__ encp,
                       const float* __restrict__ hid,
                       const float* __restrict__ attWT,
                       const float* __restrict__ enc_out,
                       const unsigned long long* __restrict__ slots,
                       const float* __restrict__ tab,
                       float* __restrict__ rnin, float* __restrict__ cat)
{
    int b = blockIdx.x, tid = threadIdx.x;
    int lane = tid & 31, w = tid >> 5;
    __shared__ float shid[Dd];
    __shared__ float shp[Aa];
    __shared__ float salpha[Ss];

    shid[tid] = hid[(size_t)b*Dd + tid];
    __syncthreads();

    float hp = 0.f;
    #pragma unroll 8
    for (int k = 0; k < Dd; k++) hp += shid[k] * attWT[(size_t)k * Aa + tid];
    shp[tid] = hp;
    __syncthreads();

    #pragma unroll
    for (int i = 0; i < 8; i++) {
        int s = w + 8 * i;
        const float* row = encp + ((size_t)b*Ss + s)*Aa;
        float acc = 0.f;
        #pragma unroll
        for (int a = lane; a < Aa; a += 32) acc += tanhf(row[a] + shp[a]);
        #pragma unroll
        for (int o = 16; o; o >>= 1) acc += __shfl_xor_sync(0xffffffffu, acc, o);
        if (lane == 0) salpha[s] = acc;
    }
    __syncthreads();
    if (w == 0) {
        float v0 = salpha[lane], v1 = salpha[lane + 32];
        float m = fmaxf(v0, v1);
        #pragma unroll
        for (int o = 16; o; o >>= 1) m = fmaxf(m, __shfl_xor_sync(0xffffffffu, m, o));
        float e0 = expf(v0 - m), e1 = expf(v1 - m);
        float sum = e0 + e1;
        #pragma unroll
        for (int o = 16; o; o >>= 1) sum += __shfl_xor_sync(0xffffffffu, sum, o);
        float inv = 1.f / sum;
        salpha[lane] = e0 * inv; salpha[lane + 32] = e1 * inv;
    }
    __syncthreads();
    float a0 = 0.f, a1 = 0.f;
    for (int s = 0; s < Ss; s++) {
        float al = salpha[s];
        const float* eo = enc_out + ((size_t)b*Ss + s)*(2*Hh);
        a0 += al * eo[tid];
        a1 += al * eo[Hh + tid];
    }
    rnin[(size_t)b*RNK + Ee + tid]      = a0;
    rnin[(size_t)b*RNK + Ee + Hh + tid] = a1;
    cat[(size_t)b*CAT + Dd + tid]       = a0;
    cat[(size_t)b*CAT + Dd + Hh + tid]  = a1;

    int tk = (int)(0xFFFFFFFFu - (unsigned)(slots[b] & 0xFFFFFFFFull));
    float e = tab[(size_t)tk * Ee + tid];
    rnin[(size_t)b*RNK + tid] = e;
    cat[(size_t)b*CAT + Dd + 2*Hh + tid] = e;
}

__global__ void logsoftmax_kernel(float* __restrict__ out)
{
    int row = blockIdx.x, tid = threadIdx.x;
    int s = row & (Ss - 1);
    float* p = out + (size_t)row * Vv;
    if (s == 0) {
        float L = logf(expf(1.f) + (float)(Vv - 1));
        for (int v = tid; v < Vv; v += 256) p[v] = (v == 0 ? 1.f : 0.f) - L;
        return;
    }
    constexpr int PT = (Vv + 255) / 256;
    float regs[PT];
    float m = -INFINITY;
    #pragma unroll
    for (int i = 0; i < PT; i++) {
        int v = tid + i * 256;
        if (v < Vv) { regs[i] = p[v]; m = fmaxf(m, regs[i]); }
        else regs[i] = -INFINITY;
    }
    __shared__ float sm[256];
    sm[tid] = m; __syncthreads();
    for (int o = 128; o; o >>= 1) { if (tid < o) sm[tid] = fmaxf(sm[tid], sm[tid+o]); __syncthreads(); }
    m = sm[0]; __syncthreads();
    float sum = 0.f;
    #pragma unroll
    for (int i = 0; i < PT; i++) {
        int v = tid + i * 256;
        if (v < Vv) sum += expf(regs[i] - m);
    }
    sm[tid] = sum; __syncthreads();
    for (int o = 128; o; o >>= 1) { if (tid < o) sm[tid] += sm[tid+o]; __syncthreads(); }
    float ls = m + logf(sm[0]);
    #pragma unroll
    for (int i = 0; i < PT; i++) {
        int v = tid + i * 256;
        if (v < Vv) p[v] = regs[i] - ls;
    }
}

// ---------------- launch helpers ------------------------------------------
static inline dim3 gridL(int M, int N) { return dim3((N + 63) / 64, M / 128); }
static inline dim3 gridSK(int M, int N) { return dim3((N + 63) / 64, M / 64); }

extern "C" void kernel_launch(void* const* d_in, const int* in_sizes, int n_in,
                              void* d_out, int out_size)
{
    const int*   inp       = (const int*)  d_in[0];
    const float* emb_table = (const float*)d_in[1];
    const float* Wih_f     = (const float*)d_in[2];
    const float* Whh_f     = (const float*)d_in[3];
    const float* bih_f     = (const float*)d_in[4];
    const float* bhh_f     = (const float*)d_in[5];
    const float* Wih_b     = (const float*)d_in[6];
    const float* Whh_b     = (const float*)d_in[7];
    const float* bih_b     = (const float*)d_in[8];
    const float* bhh_b     = (const float*)d_in[9];
    const float* fc_W      = (const float*)d_in[10];
    const float* fc_b      = (const float*)d_in[11];
    const float* attn_W    = (const float*)d_in[12];
    const float* attn_b    = (const float*)d_in[13];
    const float* dec_Wih   = (const float*)d_in[14];
    const float* dec_Whh   = (const float*)d_in[15];
    const float* dec_bih   = (const float*)d_in[16];
    const float* dec_bhh   = (const float*)d_in[17];
    const float* out_W     = (const float*)d_in[18];
    const float* out_b     = (const float*)d_in[19];
    float* out = (float*)d_out;

    float* scr = nullptr;
    cudaGetSymbolAddress((void**)&scr, g_scratch);
    float* emb   = scr + OFF_EMB;
    float* xpf   = scr + OFF_XPF;
    float* xpb   = scr + OFF_XPB;
    float* enco  = scr + OFF_ENCO;
    float* encp  = scr + OFF_ENCP;
    float* hf0   = scr + OFF_HF0;
    float* hf1   = scr + OFF_HF1;
    float* hb0   = scr + OFF_HB0;
    float* hb1   = scr + OFF_HB1;
    float* hid0  = scr + OFF_HID0;
    float* hid1  = scr + OFF_HID1;
    float* fcin  = scr + OFF_FCIN;
    float* rnin  = scr + OFF_RNIN;
    float* cat   = scr + OFF_CAT;
    float* attWT = scr + OFF_ATTWT;
    unsigned long long* slots = (unsigned long long*)(scr + OFF_SLOT);

    // ---- init + embedding + one-time GEMMs ----
    init0_kernel<<<(Bb*Hh + 255)/256, 256>>>(hf0, hb0, slots);
    embed_kernel<<<Bb*Ss, 256>>>(inp, emb_table, emb);
    transpose_attw_kernel<<<Dd, Aa>>>(attn_W, attWT);
    gemmL<<<gridL(Bb*Ss, 3*Hh), 256>>>(emb, Ee, Wih_f, Ee, xpf, 3*Hh, bih_f, Bb*Ss, 3*Hh, Ee);
    gemmL<<<gridL(Bb*Ss, 3*Hh), 256>>>(emb, Ee, Wih_b, Ee, xpb, 3*Hh, bih_b, Bb*Ss, 3*Hh, Ee);

    // ---- encoder recurrence ----
    for (int t = 0; t < Ss; t++) {
        const float* hfi = (t & 1) ? hf1 : hf0;
        const float* hbi = (t & 1) ? hb1 : hb0;
        float* hfo = (t & 1) ? hf0 : hf1;
        float* hbo = (t & 1) ? hb0 : hb1;
        enc_step_kernel<<<dim3(8, 4, 2), 256>>>(hfi, hbi, hfo, hbo,
                                                Whh_f, Whh_b, bhh_f, bhh_b,
                                                xpf, xpb, enco, t);
    }

    // ---- decoder init ----
    concat_fc_kernel<<<Bb, 256>>>(hf0, hb0, fcin);
    gemm32t<<<dim3(Dd/32, Bb/32), 256>>>(fcin, 2*Hh, fc_W, 2*Hh, hid0, Dd, fc_b, Bb, Dd, 2*Hh);

    // ---- attention projection of enc_out (one-time) ----
    gemmL<<<gridL(Bb*Ss, Aa), 256>>>(enco, 2*Hh, attn_W + Dd, Dd + 2*Hh, encp, Aa, attn_b, Bb*Ss, Aa, 2*Hh);

    // ---- decoder steps (3 launches each) ----
    for (int t = 0; t < Ss - 1; t++) {
        const float* hin = (t & 1) ? hid1 : hid0;
        float*       hout = (t & 1) ? hid0 : hid1;
        attn_embed_kernel<<<Bb, 256>>>(encp, hin, attWT, enco, slots, emb_table, rnin, cat);
        dec_fused_kernel<<<dim3(8, 4), 256>>>(rnin, hin, dec_Wih, dec_Whh,
                                              dec_bih, dec_bhh, hout, cat, slots);
        gemmSK<<<gridSK(Bb, Vv), 128>>>(cat, CAT, out_W, CAT,
                                        out + (size_t)(t + 1) * Vv, Ss * Vv, out_b,
                                        Bb, Vv, CAT, slots);
    }

    // ---- final log-softmax ----
    logsoftmax_kernel<<<Bb*Ss, 256>>>(out);
}